// round 10
// baseline (speedup 1.0000x reference)
#include <cuda_runtime.h>
#include <cuda_bf16.h>
#include <cstdint>
#include <cstddef>

#define N_NODES 50000
#define E_EDGES 400000
#define IN_DIM  384
#define HID     256
#define QDIM    384
#define HHID    128

typedef unsigned short ushort_t;

// ---------------- scratch (static device globals) ----------------------------
__device__ float  g_deg[N_NODES];
__device__ float4 g_agg[(size_t)N_NODES * IN_DIM / 4];
__device__ float4 g_h1 [(size_t)N_NODES * HID / 4];
__device__ float4 g_h2 [(size_t)N_NODES * HID / 4];
__device__ float4 g_s  [(size_t)N_NODES * HHID / 4];
__device__ float  g_qb1[HID];
__device__ float  g_qb2[HID];
__device__ float  g_qbh[HHID];
__device__ int    g_is64;
__device__ int    g_src[E_EDGES];
__device__ int    g_dst[E_EDGES];
__device__ int    g_cnt[N_NODES];
__device__ int    g_fill[N_NODES];
__device__ int    g_rowptr[N_NODES + 1];
__device__ int    g_bsum[256];
__device__ int    g_eidx[E_EDGES];
// pre-split, pre-transposed weights: [n][k] bf16 hi/lo (uint4 for 16B align)
__device__ uint4  g_wt1h[(HID * (2 * IN_DIM)) / 8];
__device__ uint4  g_wt1l[(HID * (2 * IN_DIM)) / 8];
__device__ uint4  g_wt2h[(HID * (2 * HID)) / 8];
__device__ uint4  g_wt2l[(HID * (2 * HID)) / 8];
__device__ uint4  g_wthh[(HHID * HID) / 8];
__device__ uint4  g_wthl[(HHID * HID) / 8];

// ---------------- edge-index dtype sniffing + conversion ---------------------
__global__ void detect_idx_dtype(const int* __restrict__ raw) {
    int nz = 0;
    for (int i = threadIdx.x; i < 128; i += 32)
        if (raw[2 * i + 1] != 0) nz = 1;
    #pragma unroll
    for (int o = 16; o > 0; o >>= 1) nz |= __shfl_xor_sync(0xffffffffu, nz, o);
    if (threadIdx.x == 0) g_is64 = nz ? 0 : 1;
}

__global__ void convert_idx(const void* __restrict__ raw, int E) {
    int i = blockIdx.x * blockDim.x + threadIdx.x;
    if (i >= 2 * E) return;
    int v;
    if (g_is64) v = (int)((const long long*)raw)[i];
    else        v = ((const int*)raw)[i];
    if ((unsigned)v >= (unsigned)N_NODES) v = 0;
    if (i < E) g_src[i] = v;
    else       g_dst[i - E] = v;
}

// ---------------- CSR build ---------------------------------------------------
__global__ void zero_cnt(int n) {
    int i = blockIdx.x * blockDim.x + threadIdx.x;
    if (i < n) { g_cnt[i] = 0; g_fill[i] = 0; }
}
__global__ void count_dst(int E) {
    int e = blockIdx.x * blockDim.x + threadIdx.x;
    if (e < E) atomicAdd(&g_cnt[g_dst[e]], 1);
}
__global__ void scan1(int n) {
    __shared__ int sh[256];
    int i = blockIdx.x * 256 + threadIdx.x;
    int v = (i < n) ? g_cnt[i] : 0;
    sh[threadIdx.x] = v;
    __syncthreads();
    #pragma unroll
    for (int o = 1; o < 256; o <<= 1) {
        int t = (threadIdx.x >= o) ? sh[threadIdx.x - o] : 0;
        __syncthreads();
        sh[threadIdx.x] += t;
        __syncthreads();
    }
    if (i < n) g_rowptr[i] = sh[threadIdx.x] - v;
    if (threadIdx.x == 255) g_bsum[blockIdx.x] = sh[255];
}
__global__ void scan2(int nb) {
    __shared__ int sh[256];
    int v = (threadIdx.x < nb) ? g_bsum[threadIdx.x] : 0;
    sh[threadIdx.x] = v;
    __syncthreads();
    #pragma unroll
    for (int o = 1; o < 256; o <<= 1) {
        int t = (threadIdx.x >= o) ? sh[threadIdx.x - o] : 0;
        __syncthreads();
        sh[threadIdx.x] += t;
        __syncthreads();
    }
    if (threadIdx.x < nb) g_bsum[threadIdx.x] = sh[threadIdx.x] - v;
}
__global__ void scan3(int n, int E) {
    int i = blockIdx.x * blockDim.x + threadIdx.x;
    if (i < n) {
        g_rowptr[i] += g_bsum[i >> 8];
        g_deg[i] = 1.f / ((float)g_cnt[i] + 1.f);
    }
    if (i == 0) g_rowptr[n] = E;
}
__global__ void fill_csr(int E) {
    int e = blockIdx.x * blockDim.x + threadIdx.x;
    if (e >= E) return;
    int d = g_dst[e];
    int pos = g_rowptr[d] + atomicAdd(&g_fill[d], 1);
    g_eidx[pos] = g_src[e];
}

// ---------------- gather aggregation (no atomics) -----------------------------
template<int D4PL>
__global__ void gather_agg(const float4* __restrict__ feat, int M, int D4) {
    int node = (blockIdx.x * blockDim.x + threadIdx.x) >> 5;
    int lane = threadIdx.x & 31;
    if (node >= M) return;
    float4 acc[D4PL];
    const float4* hp = feat + (size_t)node * D4;
    #pragma unroll
    for (int j = 0; j < D4PL; ++j) acc[j] = hp[lane + 32 * j];
    int beg = g_rowptr[node], end = g_rowptr[node + 1];
    for (int e = beg; e < end; ++e) {
        const float4* sp = feat + (size_t)g_eidx[e] * D4;
        #pragma unroll
        for (int j = 0; j < D4PL; ++j) {
            float4 v = sp[lane + 32 * j];
            acc[j].x += v.x; acc[j].y += v.y; acc[j].z += v.z; acc[j].w += v.w;
        }
    }
    float4* dp = g_agg + (size_t)node * D4;
    #pragma unroll
    for (int j = 0; j < D4PL; ++j) dp[lane + 32 * j] = acc[j];
}

// ---------------- weight pre-split + transpose --------------------------------
// Th[n*K + k] = hi(W[k*N + n]); Tl = lo residue. K = used (non-q) rows only.
__global__ void wsplit(const float* __restrict__ W, ushort_t* __restrict__ Th,
                       ushort_t* __restrict__ Tl, int K, int N) {
    int idx = blockIdx.x * blockDim.x + threadIdx.x;
    if (idx >= K * N) return;
    int k = idx / N, n = idx % N;
    float v = W[idx];
    __nv_bfloat16 h = __float2bfloat16_rn(v);
    __nv_bfloat16 l = __float2bfloat16_rn(v - __bfloat162float(h));
    Th[(size_t)n * K + k] = __bfloat16_as_ushort(h);
    Tl[(size_t)n * K + k] = __bfloat16_as_ushort(l);
}

// qb[j] = b[j] + sum_k q[k]*W[(qoff+k)*N + j] — warp per j
__global__ void qproj(const float* __restrict__ q, const float* __restrict__ W,
                      const float* __restrict__ b, float* __restrict__ qb,
                      int qoff, int qdim, int N) {
    int j = (blockIdx.x * blockDim.x + threadIdx.x) >> 5;
    int lane = threadIdx.x & 31;
    if (j >= N) return;
    float acc = 0.f;
    for (int k = lane; k < qdim; k += 32)
        acc = fmaf(q[k], W[(size_t)(qoff + k) * N + j], acc);
    #pragma unroll
    for (int o = 16; o > 0; o >>= 1) acc += __shfl_xor_sync(0xffffffffu, acc, o);
    if (lane == 0) qb[j] = acc + b[j];
}

// ---------------- tensor-core concat GEMM (bf16x3 split) ----------------------
// TBM=64, TBN=NN (full), TBK=16, 256 threads, 8 warps (2m x 4n), warp 32x(NN/4)
__device__ __forceinline__ void mma16816(float* d, const unsigned* a, const unsigned* b) {
    asm volatile("mma.sync.aligned.m16n8k16.row.col.f32.bf16.bf16.f32 "
                 "{%0,%1,%2,%3}, {%4,%5,%6,%7}, {%8,%9}, {%0,%1,%2,%3};"
                 : "+f"(d[0]), "+f"(d[1]), "+f"(d[2]), "+f"(d[3])
                 : "r"(a[0]), "r"(a[1]), "r"(a[2]), "r"(a[3]),
                   "r"(b[0]), "r"(b[1]));
}

__device__ __forceinline__ void split2(float x0, float x1, unsigned& hp, unsigned& lp) {
    __nv_bfloat16 h0 = __float2bfloat16_rn(x0);
    __nv_bfloat16 h1 = __float2bfloat16_rn(x1);
    __nv_bfloat16 l0 = __float2bfloat16_rn(x0 - __bfloat162float(h0));
    __nv_bfloat16 l1 = __float2bfloat16_rn(x1 - __bfloat162float(h1));
    hp = (unsigned)__bfloat16_as_ushort(h0) | ((unsigned)__bfloat16_as_ushort(h1) << 16);
    lp = (unsigned)__bfloat16_as_ushort(l0) | ((unsigned)__bfloat16_as_ushort(l1) << 16);
}

#define TBM 64
#define TBK 16
#define SPAD 24   // shorts per row: 48B stride, 16B aligned, conflict-free frags

template<int K1, int K2, int NN>
__global__ __launch_bounds__(256)
void gemm_tc(const float* __restrict__ A1,
             const float* __restrict__ A2,
             const float* __restrict__ rscale,
             const ushort_t* __restrict__ Bh,    // [NN][K1+K2]
             const ushort_t* __restrict__ Bl,
             const float* __restrict__ qb,
             float* __restrict__ out, int M)
{
    constexpr int KTOT  = K1 + K2;
    constexpr int NSTEP = KTOT / TBK;
    constexpr int WNT   = NN / 4;       // warp n extent
    constexpr int NT    = WNT / 8;      // 8 for NN=256, 4 for NN=128

    __shared__ ushort_t As_h[TBM][SPAD];
    __shared__ ushort_t As_l[TBM][SPAD];
    __shared__ ushort_t Bs_h[NN][SPAD];
    __shared__ ushort_t Bs_l[NN][SPAD];

    const int tid  = threadIdx.x;
    const int lane = tid & 31;
    const int wid  = tid >> 5;
    const int wm   = wid & 1;           // 2 x 32-row slices
    const int wn   = wid >> 1;          // 4 x WNT-col slices
    const int block_row = blockIdx.x * TBM;

    // A loader: 64 rows x 16 k floats = 256 float4, 1 per thread
    const int a_row = tid >> 2;                 // 0..63
    const int a_k   = (tid & 3) * 4;            // 0,4,8,12
    const int a_gr  = block_row + a_row;
    const bool a_ok = a_gr < M;
    const float a_rs = (K2 > 0 && a_ok) ? rscale[a_gr] : 1.f;

    float4 aF;
    uint4  bFh[2], bFl[2];

    auto loadA = [&](int kt) {
        const int kbase = kt * TBK;
        if (a_ok) {
            if (kbase < K1) {
                aF = *(const float4*)(A1 + (size_t)a_gr * K1 + kbase + a_k);
            } else {
                float4 v = *(const float4*)(A2 + (size_t)a_gr * K2 + (kbase - K1) + a_k);
                v.x *= a_rs; v.y *= a_rs; v.z *= a_rs; v.w *= a_rs;
                aF = v;
            }
        } else {
            aF = make_float4(0.f, 0.f, 0.f, 0.f);
        }
    };
    auto loadB = [&](int kt) {
        if (tid < NN) {
            const int kbase = kt * TBK;
            const uint4* ph = (const uint4*)(Bh + (size_t)tid * KTOT + kbase);
            const uint4* pl = (const uint4*)(Bl + (size_t)tid * KTOT + kbase);
            bFh[0] = ph[0]; bFh[1] = ph[1];
            bFl[0] = pl[0]; bFl[1] = pl[1];
        }
    };
    auto storeT = [&]() {
        unsigned h0, l0, h1, l1;
        split2(aF.x, aF.y, h0, l0);
        split2(aF.z, aF.w, h1, l1);
        *(uint2*)&As_h[a_row][a_k] = make_uint2(h0, h1);
        *(uint2*)&As_l[a_row][a_k] = make_uint2(l0, l1);
        if (tid < NN) {
            *(uint4*)&Bs_h[tid][0] = bFh[0];
            *(uint4*)&Bs_h[tid][8] = bFh[1];
            *(uint4*)&Bs_l[tid][0] = bFl[0];
            *(uint4*)&Bs_l[tid][8] = bFl[1];
        }
    };

    float acc[2][NT][4];
    #pragma unroll
    for (int mt = 0; mt < 2; ++mt)
        #pragma unroll
        for (int nt = 0; nt < NT; ++nt)
            #pragma unroll
            for (int r = 0; r < 4; ++r) acc[mt][nt][r] = 0.f;

    const int grp = lane >> 2;
    const int tig = lane & 3;
    const int c   = tig * 2;

    loadA(0); loadB(0);
    for (int kt = 0; kt < NSTEP; ++kt) {
        storeT();
        __syncthreads();
        if (kt + 1 < NSTEP) { loadA(kt + 1); loadB(kt + 1); }

        unsigned ah[2][4], al[2][4], bh[NT][2], bl[NT][2];
        #pragma unroll
        for (int mt = 0; mt < 2; ++mt) {
            int r = wm * 32 + mt * 16 + grp;
            ah[mt][0] = *(const unsigned*)&As_h[r][c];
            ah[mt][1] = *(const unsigned*)&As_h[r + 8][c];
            ah[mt][2] = *(const unsigned*)&As_h[r][c + 8];
            ah[mt][3] = *(const unsigned*)&As_h[r + 8][c + 8];
            al[mt][0] = *(const unsigned*)&As_l[r][c];
            al[mt][1] = *(const unsigned*)&As_l[r + 8][c];
            al[mt][2] = *(const unsigned*)&As_l[r][c + 8];
            al[mt][3] = *(const unsigned*)&As_l[r + 8][c + 8];
        }
        #pragma unroll
        for (int nt = 0; nt < NT; ++nt) {
            int n = wn * WNT + nt * 8 + grp;
            bh[nt][0] = *(const unsigned*)&Bs_h[n][c];
            bh[nt][1] = *(const unsigned*)&Bs_h[n][c + 8];
            bl[nt][0] = *(const unsigned*)&Bs_l[n][c];
            bl[nt][1] = *(const unsigned*)&Bs_l[n][c + 8];
        }
        #pragma unroll
        for (int mt = 0; mt < 2; ++mt)
            #pragma unroll
            for (int nt = 0; nt < NT; ++nt) {
                mma16816(acc[mt][nt], ah[mt], bh[nt]);
                mma16816(acc[mt][nt], ah[mt], bl[nt]);
                mma16816(acc[mt][nt], al[mt], bh[nt]);
            }
        __syncthreads();
    }

    #pragma unroll
    for (int mt = 0; mt < 2; ++mt) {
        #pragma unroll
        for (int nt = 0; nt < NT; ++nt) {
            int r0 = block_row + wm * 32 + mt * 16 + grp;
            int c0 = wn * WNT + nt * 8 + tig * 2;
            float q0 = qb[c0], q1 = qb[c0 + 1];
            if (r0 < M) {
                float2 v;
                v.x = fmaxf(acc[mt][nt][0] + q0, 0.f);
                v.y = fmaxf(acc[mt][nt][1] + q1, 0.f);
                *(float2*)(out + (size_t)r0 * NN + c0) = v;
            }
            if (r0 + 8 < M) {
                float2 v;
                v.x = fmaxf(acc[mt][nt][2] + q0, 0.f);
                v.y = fmaxf(acc[mt][nt][3] + q1, 0.f);
                *(float2*)(out + (size_t)(r0 + 8) * NN + c0) = v;
            }
        }
    }
}

// logits[i] = bh2 + sum_j s[i][j] * Wh2[j]
__global__ void head_dot(const float* __restrict__ Wh2,
                         const float* __restrict__ bh2, float* __restrict__ out, int M) {
    int warp = (blockIdx.x * blockDim.x + threadIdx.x) >> 5;
    int lane = threadIdx.x & 31;
    if (warp >= M) return;
    float4 a = g_s[(size_t)warp * (HHID / 4) + lane];
    float b0 = Wh2[lane * 4 + 0], b1 = Wh2[lane * 4 + 1];
    float b2 = Wh2[lane * 4 + 2], b3 = Wh2[lane * 4 + 3];
    float v = a.x * b0 + a.y * b1 + a.z * b2 + a.w * b3;
    #pragma unroll
    for (int o = 16; o > 0; o >>= 1) v += __shfl_xor_sync(0xffffffffu, v, o);
    if (lane == 0) out[warp] = v + bh2[0];
}

// ---------------- launch -----------------------------------------------------
extern "C" void kernel_launch(void* const* d_in, const int* in_sizes, int n_in,
                              void* d_out, int out_size)
{
    const float* x   = (const float*)d_in[0];
    const void*  ei  = d_in[1];
    const float* q   = (const float*)d_in[2];
    const float* W1  = (const float*)d_in[3];
    const float* b1  = (const float*)d_in[4];
    const float* W2  = (const float*)d_in[5];
    const float* b2  = (const float*)d_in[6];
    const float* Wh1 = (const float*)d_in[7];
    const float* bh1 = (const float*)d_in[8];
    const float* Wh2 = (const float*)d_in[9];
    const float* bh2 = (const float*)d_in[10];
    float* out = (float*)d_out;

    const int M = in_sizes[0] / IN_DIM;
    const int E = in_sizes[1] / 2;

    float  *p_deg, *p_qb1, *p_qb2, *p_qbh;
    float4 *p_agg, *p_h1, *p_h2, *p_s;
    ushort_t *p_w1h, *p_w1l, *p_w2h, *p_w2l, *p_whh, *p_whl;
    cudaGetSymbolAddress((void**)&p_deg, g_deg);
    cudaGetSymbolAddress((void**)&p_agg, g_agg);
    cudaGetSymbolAddress((void**)&p_h1,  g_h1);
    cudaGetSymbolAddress((void**)&p_h2,  g_h2);
    cudaGetSymbolAddress((void**)&p_s,   g_s);
    cudaGetSymbolAddress((void**)&p_qb1, g_qb1);
    cudaGetSymbolAddress((void**)&p_qb2, g_qb2);
    cudaGetSymbolAddress((void**)&p_qbh, g_qbh);
    cudaGetSymbolAddress((void**)&p_w1h, g_wt1h);
    cudaGetSymbolAddress((void**)&p_w1l, g_wt1l);
    cudaGetSymbolAddress((void**)&p_w2h, g_wt2h);
    cudaGetSymbolAddress((void**)&p_w2l, g_wt2l);
    cudaGetSymbolAddress((void**)&p_whh, g_wthh);
    cudaGetSymbolAddress((void**)&p_whl, g_wthl);

    const int nb = (M + 255) / 256;

    detect_idx_dtype<<<1, 32>>>((const int*)ei);
    convert_idx<<<(2 * E + 255) / 256, 256>>>(ei, E);

    zero_cnt <<<nb, 256>>>(M);
    count_dst<<<(E + 255) / 256, 256>>>(E);
    scan1    <<<nb, 256>>>(M);
    scan2    <<<1, 256>>>(nb);
    scan3    <<<nb, 256>>>(M, E);
    fill_csr <<<(E + 255) / 256, 256>>>(E);

    // weights: split + transpose once; biases with q folded
    wsplit<<<(2 * IN_DIM * HID + 255) / 256, 256>>>(W1,  p_w1h, p_w1l, 2 * IN_DIM, HID);
    wsplit<<<(2 * HID * HID + 255) / 256, 256>>>(W2,  p_w2h, p_w2l, 2 * HID, HID);
    wsplit<<<(HID * HHID + 255) / 256, 256>>>(Wh1, p_whh, p_whl, HID, HHID);
    qproj<<<(HID * 32 + 255) / 256, 256>>>(q, W1, b1, p_qb1, 2 * IN_DIM, QDIM, HID);
    qproj<<<(HID * 32 + 255) / 256, 256>>>(q, W2, b2, p_qb2, 2 * HID, QDIM, HID);
    qproj<<<(HHID * 32 + 255) / 256, 256>>>(q, Wh1, bh1, p_qbh, HID, QDIM, HHID);

    const int gx = (M + TBM - 1) / TBM;
    const int gwarp = (M * 32 + 255) / 256;

    // ---- layer 1 ----
    gather_agg<3><<<gwarp, 256>>>((const float4*)x, M, IN_DIM / 4);
    gemm_tc<IN_DIM, IN_DIM, HID><<<gx, 256>>>(
        x, (const float*)p_agg, p_deg, p_w1h, p_w1l, p_qb1, (float*)p_h1, M);

    // ---- layer 2 ----
    gather_agg<2><<<gwarp, 256>>>((const float4*)p_h1, M, HID / 4);
    gemm_tc<HID, HID, HID><<<gx, 256>>>(
        (const float*)p_h1, (const float*)p_agg, p_deg, p_w2h, p_w2l, p_qb2, (float*)p_h2, M);

    // ---- head ----
    gemm_tc<HID, 0, HHID><<<gx, 256>>>(
        (const float*)p_h2, nullptr, nullptr, p_whh, p_whl, p_qbh, (float*)p_s, M);
    head_dot<<<gwarp, 256>>>(Wh2, bh2, out, M);
}

// round 15
// speedup vs baseline: 1.5194x; 1.5194x over previous
#include <cuda_runtime.h>
#include <cuda_bf16.h>
#include <cstdint>
#include <cstddef>

#define N_NODES 50000
#define E_EDGES 400000
#define IN_DIM  384
#define HID     256
#define QDIM    384
#define HHID    128

typedef unsigned short ushort_t;

// ---------------- scratch (static device globals) ----------------------------
__device__ float  g_deg[N_NODES];
__device__ float4 g_agg[(size_t)N_NODES * IN_DIM / 4];
__device__ float4 g_h1 [(size_t)N_NODES * HID / 4];
__device__ float4 g_h2 [(size_t)N_NODES * HID / 4];
__device__ float4 g_s  [(size_t)N_NODES * HHID / 4];
__device__ float  g_qb1[HID];
__device__ float  g_qb2[HID];
__device__ float  g_qbh[HHID];
__device__ int    g_is64;
__device__ int    g_src[E_EDGES];
__device__ int    g_dst[E_EDGES];
__device__ int    g_cnt[N_NODES];
__device__ int    g_fill[N_NODES];
__device__ int    g_rowptr[N_NODES + 1];
__device__ int    g_bsum[256];
__device__ int    g_eidx[E_EDGES];
// pre-split, pre-transposed weights: [n][k] bf16 hi/lo (uint4 => 16B aligned)
__device__ uint4  g_wt1h[(HID * (2 * IN_DIM)) / 8];
__device__ uint4  g_wt1l[(HID * (2 * IN_DIM)) / 8];
__device__ uint4  g_wt2h[(HID * (2 * HID)) / 8];
__device__ uint4  g_wt2l[(HID * (2 * HID)) / 8];
__device__ uint4  g_wthh[(HHID * HID) / 8];
__device__ uint4  g_wthl[(HHID * HID) / 8];

// ---------------- edge-index dtype sniffing + conversion ---------------------
__global__ void detect_idx_dtype(const int* __restrict__ raw) {
    int nz = 0;
    for (int i = threadIdx.x; i < 128; i += 32)
        if (raw[2 * i + 1] != 0) nz = 1;
    #pragma unroll
    for (int o = 16; o > 0; o >>= 1) nz |= __shfl_xor_sync(0xffffffffu, nz, o);
    if (threadIdx.x == 0) g_is64 = nz ? 0 : 1;
}

__global__ void convert_idx(const void* __restrict__ raw, int E) {
    int i = blockIdx.x * blockDim.x + threadIdx.x;
    if (i >= 2 * E) return;
    int v;
    if (g_is64) v = (int)((const long long*)raw)[i];
    else        v = ((const int*)raw)[i];
    if ((unsigned)v >= (unsigned)N_NODES) v = 0;
    if (i < E) g_src[i] = v;
    else       g_dst[i - E] = v;
}

// ---------------- CSR build ---------------------------------------------------
__global__ void zero_cnt(int n) {
    int i = blockIdx.x * blockDim.x + threadIdx.x;
    if (i < n) { g_cnt[i] = 0; g_fill[i] = 0; }
}
__global__ void count_dst(int E) {
    int e = blockIdx.x * blockDim.x + threadIdx.x;
    if (e < E) atomicAdd(&g_cnt[g_dst[e]], 1);
}
__global__ void scan1(int n) {
    __shared__ int sh[256];
    int i = blockIdx.x * 256 + threadIdx.x;
    int v = (i < n) ? g_cnt[i] : 0;
    sh[threadIdx.x] = v;
    __syncthreads();
    #pragma unroll
    for (int o = 1; o < 256; o <<= 1) {
        int t = (threadIdx.x >= o) ? sh[threadIdx.x - o] : 0;
        __syncthreads();
        sh[threadIdx.x] += t;
        __syncthreads();
    }
    if (i < n) g_rowptr[i] = sh[threadIdx.x] - v;
    if (threadIdx.x == 255) g_bsum[blockIdx.x] = sh[255];
}
__global__ void scan2(int nb) {
    __shared__ int sh[256];
    int v = (threadIdx.x < nb) ? g_bsum[threadIdx.x] : 0;
    sh[threadIdx.x] = v;
    __syncthreads();
    #pragma unroll
    for (int o = 1; o < 256; o <<= 1) {
        int t = (threadIdx.x >= o) ? sh[threadIdx.x - o] : 0;
        __syncthreads();
        sh[threadIdx.x] += t;
        __syncthreads();
    }
    if (threadIdx.x < nb) g_bsum[threadIdx.x] = sh[threadIdx.x] - v;
}
__global__ void scan3(int n, int E) {
    int i = blockIdx.x * blockDim.x + threadIdx.x;
    if (i < n) {
        g_rowptr[i] += g_bsum[i >> 8];
        g_deg[i] = 1.f / ((float)g_cnt[i] + 1.f);
    }
    if (i == 0) g_rowptr[n] = E;
}
__global__ void fill_csr(int E) {
    int e = blockIdx.x * blockDim.x + threadIdx.x;
    if (e >= E) return;
    int d = g_dst[e];
    int pos = g_rowptr[d] + atomicAdd(&g_fill[d], 1);
    g_eidx[pos] = g_src[e];
}

// ---------------- gather aggregation (no atomics) -----------------------------
template<int D4PL>
__global__ void gather_agg(const float4* __restrict__ feat, int M, int D4) {
    int node = (blockIdx.x * blockDim.x + threadIdx.x) >> 5;
    int lane = threadIdx.x & 31;
    if (node >= M) return;
    float4 acc[D4PL];
    const float4* hp = feat + (size_t)node * D4;
    #pragma unroll
    for (int j = 0; j < D4PL; ++j) acc[j] = hp[lane + 32 * j];
    int beg = g_rowptr[node], end = g_rowptr[node + 1];
    for (int e = beg; e < end; ++e) {
        const float4* sp = feat + (size_t)g_eidx[e] * D4;
        #pragma unroll
        for (int j = 0; j < D4PL; ++j) {
            float4 v = sp[lane + 32 * j];
            acc[j].x += v.x; acc[j].y += v.y; acc[j].z += v.z; acc[j].w += v.w;
        }
    }
    float4* dp = g_agg + (size_t)node * D4;
    #pragma unroll
    for (int j = 0; j < D4PL; ++j) dp[lane + 32 * j] = acc[j];
}

// ---------------- weight pre-split + transpose --------------------------------
__global__ void wsplit(const float* __restrict__ W, ushort_t* __restrict__ Th,
                       ushort_t* __restrict__ Tl, int K, int N) {
    int idx = blockIdx.x * blockDim.x + threadIdx.x;
    if (idx >= K * N) return;
    int k = idx / N, n = idx % N;
    float v = W[idx];
    __nv_bfloat16 h = __float2bfloat16_rn(v);
    __nv_bfloat16 l = __float2bfloat16_rn(v - __bfloat162float(h));
    Th[(size_t)n * K + k] = __bfloat16_as_ushort(h);
    Tl[(size_t)n * K + k] = __bfloat16_as_ushort(l);
}

// qb[j] = b[j] + sum_k q[k]*W[(qoff+k)*N + j] — warp per j
__global__ void qproj(const float* __restrict__ q, const float* __restrict__ W,
                      const float* __restrict__ b, float* __restrict__ qb,
                      int qoff, int qdim, int N) {
    int j = (blockIdx.x * blockDim.x + threadIdx.x) >> 5;
    int lane = threadIdx.x & 31;
    if (j >= N) return;
    float acc = 0.f;
    for (int k = lane; k < qdim; k += 32)
        acc = fmaf(q[k], W[(size_t)(qoff + k) * N + j], acc);
    #pragma unroll
    for (int o = 16; o > 0; o >>= 1) acc += __shfl_xor_sync(0xffffffffu, acc, o);
    if (lane == 0) qb[j] = acc + b[j];
}

// ---------------- tensor-core concat GEMM (bf16x3 split) ---------------------
// A: fp32 in-kernel split. B: pre-split bf16 [n][k], pure copy.
// Block 128x64, 8 warps (4m x 2n), warp tile 32x32, m16n8k16, BK=32.
__device__ __forceinline__ void mma16816(float* d, const unsigned* a, const unsigned* b) {
    asm volatile("mma.sync.aligned.m16n8k16.row.col.f32.bf16.bf16.f32 "
                 "{%0,%1,%2,%3}, {%4,%5,%6,%7}, {%8,%9}, {%0,%1,%2,%3};"
                 : "+f"(d[0]), "+f"(d[1]), "+f"(d[2]), "+f"(d[3])
                 : "r"(a[0]), "r"(a[1]), "r"(a[2]), "r"(a[3]),
                   "r"(b[0]), "r"(b[1]));
}

__device__ __forceinline__ void split2(float x0, float x1, unsigned& hp, unsigned& lp) {
    __nv_bfloat16 h0 = __float2bfloat16_rn(x0);
    __nv_bfloat16 h1 = __float2bfloat16_rn(x1);
    __nv_bfloat16 l0 = __float2bfloat16_rn(x0 - __bfloat162float(h0));
    __nv_bfloat16 l1 = __float2bfloat16_rn(x1 - __bfloat162float(h1));
    hp = (unsigned)__bfloat16_as_ushort(h0) | ((unsigned)__bfloat16_as_ushort(h1) << 16);
    lp = (unsigned)__bfloat16_as_ushort(l0) | ((unsigned)__bfloat16_as_ushort(l1) << 16);
}

#define TBM 128
#define TBN 64
#define TBK 32
#define SPAD 40   // 80B row stride: 16B-aligned uint4 stores, conflict-free frags

template<int K1, int K2, int NN>
__global__ __launch_bounds__(256)
void gemm_cat_tc(const float* __restrict__ A1,
                 const float* __restrict__ A2,
                 const float* __restrict__ rscale,
                 const ushort_t* __restrict__ Bh,   // [NN][K1+K2] pre-split
                 const ushort_t* __restrict__ Bl,
                 const float* __restrict__ qb,
                 float* __restrict__ out, int M)
{
    constexpr int KTOT = K1 + K2;
    constexpr int NSTEP = KTOT / TBK;

    __shared__ ushort_t As_h[TBM][SPAD];
    __shared__ ushort_t As_l[TBM][SPAD];
    __shared__ ushort_t Bs_h[TBN][SPAD];   // [n][k]
    __shared__ ushort_t Bs_l[TBN][SPAD];

    const int tid  = threadIdx.x;
    const int lane = tid & 31;
    const int wid  = tid >> 5;
    const int wm   = wid & 3;
    const int wn   = wid >> 2;
    const int block_row = blockIdx.x * TBM;
    const int block_col = blockIdx.y * TBN;

    // A loader: 128 rows x 32 k floats = 1024 float4, 4 per thread
    int a_row[4], a_k[4];
    bool a_ok[4];
    float a_rs[4];
    #pragma unroll
    for (int i = 0; i < 4; ++i) {
        int idx = i * 256 + tid;
        a_row[i] = idx >> 3;
        a_k[i]   = (idx & 3) * 4 + ((idx >> 2) & 1) * 16;   // 0..28, 4-float quads
        int gr = block_row + a_row[i];
        a_ok[i] = gr < M;
        a_rs[i] = (K2 > 0 && a_ok[i]) ? rscale[gr] : 1.f;
    }
    // B loader: 64 n x 32 k shorts per buffer = 256 uint4, 1 per thread
    const int b_n = tid >> 2;
    const int b_q = (tid & 3) * 8;

    float4 aF[4];
    uint4  bFh, bFl;

    auto loadTiles = [&](int kt) {
        const int kbase = kt * TBK;
        const bool inA1 = kbase < K1;
        #pragma unroll
        for (int i = 0; i < 4; ++i) {
            if (a_ok[i]) {
                int gr = block_row + a_row[i];
                if (inA1) {
                    aF[i] = *(const float4*)(A1 + (size_t)gr * K1 + kbase + a_k[i]);
                } else {
                    float4 v = *(const float4*)(A2 + (size_t)gr * K2 + (kbase - K1) + a_k[i]);
                    float rs = a_rs[i];
                    v.x *= rs; v.y *= rs; v.z *= rs; v.w *= rs;
                    aF[i] = v;
                }
            } else {
                aF[i] = make_float4(0.f, 0.f, 0.f, 0.f);
            }
        }
        bFh = *(const uint4*)(Bh + (size_t)(block_col + b_n) * KTOT + kbase + b_q);
        bFl = *(const uint4*)(Bl + (size_t)(block_col + b_n) * KTOT + kbase + b_q);
    };

    auto storeTiles = [&]() {
        #pragma unroll
        for (int i = 0; i < 4; ++i) {
            unsigned h0, l0, h1, l1;
            split2(aF[i].x, aF[i].y, h0, l0);
            split2(aF[i].z, aF[i].w, h1, l1);
            *(uint2*)&As_h[a_row[i]][a_k[i]] = make_uint2(h0, h1);
            *(uint2*)&As_l[a_row[i]][a_k[i]] = make_uint2(l0, l1);
        }
        *(uint4*)&Bs_h[b_n][b_q] = bFh;
        *(uint4*)&Bs_l[b_n][b_q] = bFl;
    };

    float acc[2][4][4];
    #pragma unroll
    for (int mt = 0; mt < 2; ++mt)
        #pragma unroll
        for (int nt = 0; nt < 4; ++nt)
            #pragma unroll
            for (int r = 0; r < 4; ++r) acc[mt][nt][r] = 0.f;

    const int grp = lane >> 2;
    const int tig = lane & 3;

    loadTiles(0);
    for (int kt = 0; kt < NSTEP; ++kt) {
        storeTiles();
        __syncthreads();
        if (kt + 1 < NSTEP) loadTiles(kt + 1);

        #pragma unroll
        for (int kk = 0; kk < 2; ++kk) {
            const int c = kk * 16 + tig * 2;
            unsigned ah[2][4], al[2][4], bh[4][2], bl[4][2];
            #pragma unroll
            for (int mt = 0; mt < 2; ++mt) {
                int r = wm * 32 + mt * 16 + grp;
                ah[mt][0] = *(const unsigned*)&As_h[r][c];
                ah[mt][1] = *(const unsigned*)&As_h[r + 8][c];
                ah[mt][2] = *(const unsigned*)&As_h[r][c + 8];
                ah[mt][3] = *(const unsigned*)&As_h[r + 8][c + 8];
                al[mt][0] = *(const unsigned*)&As_l[r][c];
                al[mt][1] = *(const unsigned*)&As_l[r + 8][c];
                al[mt][2] = *(const unsigned*)&As_l[r][c + 8];
                al[mt][3] = *(const unsigned*)&As_l[r + 8][c + 8];
            }
            #pragma unroll
            for (int nt = 0; nt < 4; ++nt) {
                int n = wn * 32 + nt * 8 + grp;
                bh[nt][0] = *(const unsigned*)&Bs_h[n][c];
                bh[nt][1] = *(const unsigned*)&Bs_h[n][c + 8];
                bl[nt][0] = *(const unsigned*)&Bs_l[n][c];
                bl[nt][1] = *(const unsigned*)&Bs_l[n][c + 8];
            }
            #pragma unroll
            for (int mt = 0; mt < 2; ++mt)
                #pragma unroll
                for (int nt = 0; nt < 4; ++nt) {
                    mma16816(acc[mt][nt], ah[mt], bh[nt]);
                    mma16816(acc[mt][nt], ah[mt], bl[nt]);
                    mma16816(acc[mt][nt], al[mt], bh[nt]);
                }
        }
        __syncthreads();
    }

    #pragma unroll
    for (int mt = 0; mt < 2; ++mt) {
        #pragma unroll
        for (int nt = 0; nt < 4; ++nt) {
            int r0 = block_row + wm * 32 + mt * 16 + grp;
            int c0 = block_col + wn * 32 + nt * 8 + tig * 2;
            float q0 = qb[c0], q1 = qb[c0 + 1];
            if (r0 < M) {
                float2 v;
                v.x = fmaxf(acc[mt][nt][0] + q0, 0.f);
                v.y = fmaxf(acc[mt][nt][1] + q1, 0.f);
                *(float2*)(out + (size_t)r0 * NN + c0) = v;
            }
            if (r0 + 8 < M) {
                float2 v;
                v.x = fmaxf(acc[mt][nt][2] + q0, 0.f);
                v.y = fmaxf(acc[mt][nt][3] + q1, 0.f);
                *(float2*)(out + (size_t)(r0 + 8) * NN + c0) = v;
            }
        }
    }
}

// logits[i] = bh2 + sum_j s[i][j] * Wh2[j]
__global__ void head_dot(const float* __restrict__ Wh2,
                         const float* __restrict__ bh2, float* __restrict__ out, int M) {
    int warp = (blockIdx.x * blockDim.x + threadIdx.x) >> 5;
    int lane = threadIdx.x & 31;
    if (warp >= M) return;
    float4 a = g_s[(size_t)warp * (HHID / 4) + lane];
    float b0 = Wh2[lane * 4 + 0], b1 = Wh2[lane * 4 + 1];
    float b2 = Wh2[lane * 4 + 2], b3 = Wh2[lane * 4 + 3];
    float v = a.x * b0 + a.y * b1 + a.z * b2 + a.w * b3;
    #pragma unroll
    for (int o = 16; o > 0; o >>= 1) v += __shfl_xor_sync(0xffffffffu, v, o);
    if (lane == 0) out[warp] = v + bh2[0];
}

// ---------------- launch -----------------------------------------------------
extern "C" void kernel_launch(void* const* d_in, const int* in_sizes, int n_in,
                              void* d_out, int out_size)
{
    const float* x   = (const float*)d_in[0];
    const void*  ei  = d_in[1];
    const float* q   = (const float*)d_in[2];
    const float* W1  = (const float*)d_in[3];
    const float* b1  = (const float*)d_in[4];
    const float* W2  = (const float*)d_in[5];
    const float* b2  = (const float*)d_in[6];
    const float* Wh1 = (const float*)d_in[7];
    const float* bh1 = (const float*)d_in[8];
    const float* Wh2 = (const float*)d_in[9];
    const float* bh2 = (const float*)d_in[10];
    float* out = (float*)d_out;

    const int M = in_sizes[0] / IN_DIM;
    const int E = in_sizes[1] / 2;

    float  *p_deg, *p_qb1, *p_qb2, *p_qbh;
    float4 *p_agg, *p_h1, *p_h2, *p_s;
    ushort_t *p_w1h, *p_w1l, *p_w2h, *p_w2l, *p_whh, *p_whl;
    cudaGetSymbolAddress((void**)&p_deg, g_deg);
    cudaGetSymbolAddress((void**)&p_agg, g_agg);
    cudaGetSymbolAddress((void**)&p_h1,  g_h1);
    cudaGetSymbolAddress((void**)&p_h2,  g_h2);
    cudaGetSymbolAddress((void**)&p_s,   g_s);
    cudaGetSymbolAddress((void**)&p_qb1, g_qb1);
    cudaGetSymbolAddress((void**)&p_qb2, g_qb2);
    cudaGetSymbolAddress((void**)&p_qbh, g_qbh);
    cudaGetSymbolAddress((void**)&p_w1h, g_wt1h);
    cudaGetSymbolAddress((void**)&p_w1l, g_wt1l);
    cudaGetSymbolAddress((void**)&p_w2h, g_wt2h);
    cudaGetSymbolAddress((void**)&p_w2l, g_wt2l);
    cudaGetSymbolAddress((void**)&p_whh, g_wthh);
    cudaGetSymbolAddress((void**)&p_whl, g_wthl);

    const int nb = (M + 255) / 256;

    detect_idx_dtype<<<1, 32>>>((const int*)ei);
    convert_idx<<<(2 * E + 255) / 256, 256>>>(ei, E);

    zero_cnt <<<nb, 256>>>(M);
    count_dst<<<(E + 255) / 256, 256>>>(E);
    scan1    <<<nb, 256>>>(M);
    scan2    <<<1, 256>>>(nb);
    scan3    <<<nb, 256>>>(M, E);
    fill_csr <<<(E + 255) / 256, 256>>>(E);

    wsplit<<<(2 * IN_DIM * HID + 255) / 256, 256>>>(W1,  p_w1h, p_w1l, 2 * IN_DIM, HID);
    wsplit<<<(2 * HID * HID + 255) / 256, 256>>>(W2,  p_w2h, p_w2l, 2 * HID, HID);
    wsplit<<<(HID * HHID + 255) / 256, 256>>>(Wh1, p_whh, p_whl, HID, HHID);
    qproj<<<(HID * 32 + 255) / 256, 256>>>(q, W1, b1, p_qb1, 2 * IN_DIM, QDIM, HID);
    qproj<<<(HID * 32 + 255) / 256, 256>>>(q, W2, b2, p_qb2, 2 * HID, QDIM, HID);
    qproj<<<(HHID * 32 + 255) / 256, 256>>>(q, Wh1, bh1, p_qbh, HID, QDIM, HHID);

    const int gx = (M + TBM - 1) / TBM;
    const int gwarp = (M * 32 + 255) / 256;

    // ---- layer 1 ----
    gather_agg<3><<<gwarp, 256>>>((const float4*)x, M, IN_DIM / 4);
    gemm_cat_tc<IN_DIM, IN_DIM, HID><<<dim3(gx, HID / TBN), 256>>>(
        x, (const float*)p_agg, p_deg, p_w1h, p_w1l, p_qb1, (float*)p_h1, M);

    // ---- layer 2 ----
    gather_agg<2><<<gwarp, 256>>>((const float4*)p_h1, M, HID / 4);
    gemm_cat_tc<HID, HID, HID><<<dim3(gx, HID / TBN), 256>>>(
        (const float*)p_h1, (const float*)p_agg, p_deg, p_w2h, p_w2l, p_qb2, (float*)p_h2, M);

    // ---- head ----
    gemm_cat_tc<HID, 0, HHID><<<dim3(gx, HHID / TBN), 256>>>(
        (const float*)p_h2, nullptr, nullptr, p_whh, p_whl, p_qbh, (float*)p_s, M);
    head_dot<<<gwarp, 256>>>(Wh2, bh2, out, M);
}